// round 12
// baseline (speedup 1.0000x reference)
#include <cuda_runtime.h>
#include <cuda_bf16.h>
#include <cstdint>
#include <math.h>

#define D_MODEL 1024
#define NHEADS  16
#define DEPTH   64
#define BATCH   2
#define SEQ     2048
#define MTOT    (BATCH*SEQ)   // 4096

// ---------------- scratch (device globals; no allocations allowed) ----------
__device__ float g_q[BATCH*NHEADS*SEQ*DEPTH];   // 16 MB, [B,H,S,64]
__device__ float g_k[BATCH*NHEADS*SEQ*DEPTH];
__device__ float g_v[BATCH*NHEADS*SEQ*DEPTH];
__device__ float g_ctx[BATCH*SEQ*D_MODEL];      // 16 MB, [B,S,1024]

// ---------------- helpers ----------------------------------------------------
__device__ __forceinline__ void mma_bf16_16x8x16(float* d, const uint32_t* a,
                                                 const uint32_t* b) {
    asm volatile(
        "mma.sync.aligned.m16n8k16.row.col.f32.bf16.bf16.f32 "
        "{%0,%1,%2,%3}, {%4,%5,%6,%7}, {%8,%9}, {%0,%1,%2,%3};"
        : "+f"(d[0]), "+f"(d[1]), "+f"(d[2]), "+f"(d[3])
        : "r"(a[0]), "r"(a[1]), "r"(a[2]), "r"(a[3]), "r"(b[0]), "r"(b[1]));
}
__device__ __forceinline__ void ldm_x4(uint32_t* r, uint32_t saddr) {
    asm volatile("ldmatrix.sync.aligned.m8n8.x4.shared.b16 {%0,%1,%2,%3}, [%4];"
        : "=r"(r[0]), "=r"(r[1]), "=r"(r[2]), "=r"(r[3]) : "r"(saddr));
}
__device__ __forceinline__ void ldm_x4_t(uint32_t* r, uint32_t saddr) {
    asm volatile("ldmatrix.sync.aligned.m8n8.x4.trans.shared.b16 {%0,%1,%2,%3}, [%4];"
        : "=r"(r[0]), "=r"(r[1]), "=r"(r[2]), "=r"(r[3]) : "r"(saddr));
}
__device__ __forceinline__ uint32_t smem_u32(const void* p) {
    uint32_t a;
    asm("{ .reg .u64 t; cvta.to.shared.u64 t, %1; cvt.u32.u64 %0, t; }"
        : "=r"(a) : "l"(p));
    return a;
}
// pack two floats into bf16x2 (a -> low half, b -> high half), plus residual pack
__device__ __forceinline__ uint32_t bf2pack(float a, float b) {
    uint32_t p;
    asm("cvt.rn.bf16x2.f32 %0, %1, %2;" : "=r"(p) : "f"(b), "f"(a));
    return p;
}
__device__ __forceinline__ void split_pack(float a, float b, uint32_t& hi, uint32_t& lo) {
    hi = bf2pack(a, b);
    const float fa = __uint_as_float(hi << 16);
    const float fb = __uint_as_float(hi & 0xffff0000u);
    lo = bf2pack(a - fa, b - fb);
}

// ============ split-bf16 3-MMA projection: out = A @ W^T + bias =============
// CTA 128x128, 8 warps (2x4), warp 64x32. K staged 16 per stage, LDG-prefetch
// double buffer; operands stored as bf16 hi/lo pairs; error ~2^-17.
// PFL=24 bf16 -> 48-byte rows: 16B-aligned ldmatrix rows, conflict-free.
constexpr int PBM = 128, PBN = 128, PBK = 16;
constexpr int PFL  = 24;                 // bf16 row stride
constexpr int PSTG = 128 * PFL;          // 3072 bf16 per buffer
// stage s base (bf16 units) = (s&1)*4*PSTG; within: Ahi +0, Alo +PSTG, Bhi +2*PSTG, Blo +3*PSTG
constexpr int PROJ_SMEM = 2 * 4 * PSTG * 2;   // 49152 bytes

template<int SPLIT>
__device__ __forceinline__
void proj_body(uint16_t* sb, const float* __restrict__ A, const float* __restrict__ W,
               const float* __restrict__ bias, float* __restrict__ out) {
    const int tid  = threadIdx.x;
    const int wid  = tid >> 5;
    const int lane = tid & 31;
    const int g    = lane >> 2;
    const int tg   = lane & 3;
    const int wm   = wid >> 2;
    const int wn   = wid & 3;
    const int bm   = blockIdx.y * PBM;
    const int bn   = blockIdx.x * PBN;

    const uint32_t smb = smem_u32(sb);
    // A fragment pattern: row = wm*64+mi*16+(lane&15), col8 = (lane>>4)*8
    uint32_t aAddr[4];
    #pragma unroll
    for (int mi = 0; mi < 4; mi++)
        aAddr[mi] = smb + ((wm*64 + mi*16 + (lane & 15)) * PFL + (lane >> 4) * 8) * 2;
    // B fragment pattern: row = wn*32+u*16+(lane>>4)*8+(lane&7), col8 = ((lane>>3)&1)*8
    uint32_t bAddr[2];
    #pragma unroll
    for (int u = 0; u < 2; u++)
        bAddr[u] = smb + (2*PSTG + (wn*32 + u*16 + (lane >> 4)*8 + (lane & 7)) * PFL
                          + ((lane >> 3) & 1) * 8) * 2;

    float acc[4][4][4] = {};
    float4 areg[2], wreg[2];

    // preload stage 0
    #pragma unroll
    for (int i = 0; i < 2; i++) {
        const int idx = tid + i * 256;
        const int r = idx >> 2, c = (idx & 3) * 4;
        areg[i] = *(const float4*)(A + (size_t)(bm + r) * D_MODEL + c);
        wreg[i] = *(const float4*)(W + (size_t)(bn + r) * D_MODEL + c);
    }

    for (int s = 0; s < D_MODEL / PBK; s++) {     // 64 stages
        const int base = (s & 1) * 4 * PSTG;
        __syncthreads();   // prior MMAs done with this buffer
        #pragma unroll
        for (int i = 0; i < 2; i++) {
            const int idx = tid + i * 256;
            const int r = idx >> 2, c = (idx & 3) * 4;
            uint2 hi, lo;
            split_pack(areg[i].x, areg[i].y, hi.x, lo.x);
            split_pack(areg[i].z, areg[i].w, hi.y, lo.y);
            *(uint2*)(sb + base + r * PFL + c)        = hi;
            *(uint2*)(sb + base + PSTG + r * PFL + c) = lo;
            split_pack(wreg[i].x, wreg[i].y, hi.x, lo.x);
            split_pack(wreg[i].z, wreg[i].w, hi.y, lo.y);
            *(uint2*)(sb + base + 2*PSTG + r * PFL + c) = hi;
            *(uint2*)(sb + base + 3*PSTG + r * PFL + c) = lo;
        }
        __syncthreads();

        // prefetch next stage (overlaps MMAs)
        if (s + 1 < D_MODEL / PBK) {
            const int k0 = (s + 1) * PBK;
            #pragma unroll
            for (int i = 0; i < 2; i++) {
                const int idx = tid + i * 256;
                const int r = idx >> 2, c = (idx & 3) * 4;
                areg[i] = *(const float4*)(A + (size_t)(bm + r) * D_MODEL + k0 + c);
                wreg[i] = *(const float4*)(W + (size_t)(bn + r) * D_MODEL + k0 + c);
            }
        }

        const uint32_t bufo = (uint32_t)base * 2;
        uint32_t bh[2][4], bl[2][4];
        #pragma unroll
        for (int u = 0; u < 2; u++) {
            ldm_x4(bh[u], bAddr[u] + bufo);
            ldm_x4(bl[u], bAddr[u] + bufo + PSTG * 2);
        }
        #pragma unroll
        for (int mi = 0; mi < 4; mi++) {
            uint32_t ah[4], al[4];
            ldm_x4(ah, aAddr[mi] + bufo);
            ldm_x4(al, aAddr[mi] + bufo + PSTG * 2);
            #pragma unroll
            for (int ni = 0; ni < 4; ni++) {
                const uint32_t* bhp = bh[ni >> 1] + (ni & 1) * 2;
                const uint32_t* blp = bl[ni >> 1] + (ni & 1) * 2;
                mma_bf16_16x8x16(acc[mi][ni], ah, bhp);
                mma_bf16_16x8x16(acc[mi][ni], al, bhp);
                mma_bf16_16x8x16(acc[mi][ni], ah, blp);
            }
        }
    }
    __syncthreads();

    #pragma unroll
    for (int mi = 0; mi < 4; mi++) {
        #pragma unroll
        for (int ni = 0; ni < 4; ni++) {
            const int col = bn + wn * 32 + ni * 8 + tg * 2;
            const float2 bv = *(const float2*)(bias + col);
            #pragma unroll
            for (int half = 0; half < 2; half++) {
                const int m = bm + wm * 64 + mi * 16 + g + half * 8;
                float2 o;
                o.x = acc[mi][ni][half * 2 + 0] + bv.x;
                o.y = acc[mi][ni][half * 2 + 1] + bv.y;
                if (SPLIT) {
                    const int b = m >> 11, sq = m & 2047;
                    const int h = col >> 6, d = col & 63;
                    *(float2*)(out + (((size_t)(b * NHEADS + h) * SEQ) + sq) * DEPTH + d) = o;
                } else {
                    *(float2*)(out + (size_t)m * D_MODEL + col) = o;
                }
            }
        }
    }
}

__global__ __launch_bounds__(256)
void proj_qkv(const float* __restrict__ q, const float* __restrict__ k,
              const float* __restrict__ v,
              const float* __restrict__ Wq, const float* __restrict__ bq,
              const float* __restrict__ Wk, const float* __restrict__ bk,
              const float* __restrict__ Wv, const float* __restrict__ bv) {
    extern __shared__ uint16_t sbm[];
    const float *A, *W, *bias;
    float* out;
    if (blockIdx.z == 0)      { A = q; W = Wq; bias = bq; out = g_q; }
    else if (blockIdx.z == 1) { A = k; W = Wk; bias = bk; out = g_k; }
    else                      { A = v; W = Wv; bias = bv; out = g_v; }
    proj_body<1>(sbm, A, W, bias, out);
}

__global__ __launch_bounds__(256)
void proj_o(const float* __restrict__ W, const float* __restrict__ bias,
            float* __restrict__ out) {
    extern __shared__ uint16_t sbm[];
    proj_body<0>(sbm, g_ctx, W, bias, out);
}

// ================= flash attention v8: split-bf16, P in registers ===========
constexpr int FQ  = 128;
constexpr int FK  = 64;
constexpr int FL  = 72;                       // row stride in bf16 units (144B)

constexpr int W_QH = 0;
constexpr int W_QL = W_QH + FQ * FL;          // 9216
constexpr int W_KH = W_QL + FQ * FL;          // 18432
constexpr int W_KL = W_KH + FK * FL;          // 23040
constexpr int W_VH = W_KL + FK * FL;          // 27648
constexpr int W_VL = W_VH + FK * FL;          // 32256
constexpr int SM_END = W_VL + FK * FL;        // 36864 bf16 units
constexpr int PEN_B  = SM_END * 2;
constexpr int FLASH_SMEM = PEN_B + FK * 4;    // 73984 bytes

constexpr uint32_t QLOFF = (W_QL - W_QH) * 2;
constexpr uint32_t KLOFF = (W_KL - W_KH) * 2;
constexpr uint32_t VLOFF = (W_VL - W_VH) * 2;

__global__ __launch_bounds__(256, 2)
void flash_mma(const int* __restrict__ mask) {
    extern __shared__ uint32_t sw[];
    uint16_t* sb = (uint16_t*)sw;
    float* pen = (float*)((char*)sw + PEN_B);

    const int qt = blockIdx.x, h = blockIdx.y, b = blockIdx.z;
    const int tid  = threadIdx.x;
    const int w    = tid >> 5;
    const int lane = tid & 31;
    const int tg   = lane & 3;
    const int g    = lane >> 2;

    const uint32_t swb = smem_u32(sw);
    const uint32_t arow = w*16 + (lane & 15);
    const uint32_t acol = (lane >> 4) * 8;
    const uint32_t qA = swb + (W_QH + arow * FL + acol) * 2;
    uint32_t kA[4];
    #pragma unroll
    for (int u = 0; u < 4; u++)
        kA[u] = swb + (W_KH + (u*16 + (lane >> 4) * 8 + (lane & 7)) * FL
                       + ((lane >> 3) & 1) * 8) * 2;
    uint32_t vA[4];
    #pragma unroll
    for (int u = 0; u < 4; u++)
        vA[u] = swb + (W_VH + (((lane >> 3) & 1) * 8 + (lane & 7)) * FL
                       + u*16 + (lane >> 4) * 8) * 2;

    const float* qbase = g_q + ((size_t)(b*NHEADS + h) * SEQ + qt*FQ) * DEPTH;
    const float* kbase = g_k + (size_t)(b*NHEADS + h) * SEQ * DEPTH;
    const float* vbase = g_v + (size_t)(b*NHEADS + h) * SEQ * DEPTH;

    // stage Q (scaled by 1/8), split bf16 hi/lo
    #pragma unroll
    for (int i = 0; i < 8; i++) {
        const int idx = tid + i * 256;
        const int r = idx >> 4, c4 = (idx & 15) << 2;
        float4 v = *(const float4*)(qbase + r * DEPTH + c4);
        v.x *= 0.125f; v.y *= 0.125f; v.z *= 0.125f; v.w *= 0.125f;
        uint2 hi, lo;
        split_pack(v.x, v.y, hi.x, lo.x);
        split_pack(v.z, v.w, hi.y, lo.y);
        *(uint2*)(sb + W_QH + r * FL + c4) = hi;
        *(uint2*)(sb + W_QL + r * FL + c4) = lo;
    }

    // prefetch K/V tile 0 + mask word
    float4 kreg[4], vreg[4];
    #pragma unroll
    for (int j = 0; j < 4; j++) {
        const int slot = tid + j * 256;
        const int r = slot >> 4, c4 = (slot & 15) << 2;
        kreg[j] = *(const float4*)(kbase + (size_t)r * DEPTH + c4);
        vreg[j] = *(const float4*)(vbase + (size_t)r * DEPTH + c4);
    }
    int pmask = (tid < FK) ? mask[b*SEQ + tid] : 0;

    float m0 = -1e30f, m1 = -1e30f, l0 = 0.f, l1 = 0.f;
    float oac[8][4] = {};

    for (int kt = 0; kt < SEQ / FK; kt++) {
        __syncthreads();
        #pragma unroll
        for (int j = 0; j < 4; j++) {
            const int slot = tid + j * 256;
            const int r = slot >> 4, c4 = (slot & 15) << 2;
            uint2 khi, klo, vhi, vlo;
            split_pack(kreg[j].x, kreg[j].y, khi.x, klo.x);
            split_pack(kreg[j].z, kreg[j].w, khi.y, klo.y);
            split_pack(vreg[j].x, vreg[j].y, vhi.x, vlo.x);
            split_pack(vreg[j].z, vreg[j].w, vhi.y, vlo.y);
            *(uint2*)(sb + W_KH + r * FL + c4) = khi;
            *(uint2*)(sb + W_KL + r * FL + c4) = klo;
            *(uint2*)(sb + W_VH + r * FL + c4) = vhi;
            *(uint2*)(sb + W_VL + r * FL + c4) = vlo;
        }
        if (tid < FK)
            pen[tid] = -1e9f * (float)pmask;
        __syncthreads();

        // prefetch next tile (overlaps with MMAs)
        if (kt + 1 < SEQ / FK) {
            const float* kb2 = kbase + (size_t)(kt + 1) * FK * DEPTH;
            const float* vb2 = vbase + (size_t)(kt + 1) * FK * DEPTH;
            #pragma unroll
            for (int j = 0; j < 4; j++) {
                const int slot = tid + j * 256;
                const int r = slot >> 4, c4 = (slot & 15) << 2;
                kreg[j] = *(const float4*)(kb2 + (size_t)r * DEPTH + c4);
                vreg[j] = *(const float4*)(vb2 + (size_t)r * DEPTH + c4);
            }
            if (tid < FK) pmask = mask[b*SEQ + (kt + 1)*FK + tid];
        }

        // ---- S = Q @ K^T : qh@kh + ql@kh + qh@kl ----
        float sac[8][4] = {};
        #pragma unroll
        for (int ks = 0; ks < 4; ks++) {
            uint32_t qh[4], ql[4];
            ldm_x4(qh, qA + ks * 32);
            ldm_x4(ql, qA + ks * 32 + QLOFF);
            #pragma unroll
            for (int u = 0; u < 4; u++) {
                uint32_t kh[4], kl[4];
                ldm_x4(kh, kA[u] + ks * 32);
                ldm_x4(kl, kA[u] + ks * 32 + KLOFF);
                mma_bf16_16x8x16(sac[2*u],     qh, kh);
                mma_bf16_16x8x16(sac[2*u],     ql, kh);
                mma_bf16_16x8x16(sac[2*u],     qh, kl);
                mma_bf16_16x8x16(sac[2*u + 1], qh, kh + 2);
                mma_bf16_16x8x16(sac[2*u + 1], ql, kh + 2);
                mma_bf16_16x8x16(sac[2*u + 1], qh, kl + 2);
            }
        }

        // ---- mask + online softmax; pack P hi/lo directly into A-fragments --
        #pragma unroll
        for (int nf = 0; nf < 8; nf++) {
            const float2 pe = *(const float2*)&pen[nf*8 + 2*tg];
            sac[nf][0] += pe.x; sac[nf][1] += pe.y;
            sac[nf][2] += pe.x; sac[nf][3] += pe.y;
        }
        float mx0 = -1e30f, mx1 = -1e30f;
        #pragma unroll
        for (int nf = 0; nf < 8; nf++) {
            mx0 = fmaxf(mx0, fmaxf(sac[nf][0], sac[nf][1]));
            mx1 = fmaxf(mx1, fmaxf(sac[nf][2], sac[nf][3]));
        }
        mx0 = fmaxf(mx0, __shfl_xor_sync(0xffffffffu, mx0, 1));
        mx0 = fmaxf(mx0, __shfl_xor_sync(0xffffffffu, mx0, 2));
        mx1 = fmaxf(mx1, __shfl_xor_sync(0xffffffffu, mx1, 1));
        mx1 = fmaxf(mx1, __shfl_xor_sync(0xffffffffu, mx1, 2));
        const float mn0 = fmaxf(m0, mx0), mn1 = fmaxf(m1, mx1);
        const float c0 = __expf(m0 - mn0), c1 = __expf(m1 - mn1);
        float s0 = 0.f, s1 = 0.f;
        uint32_t ph[4][4], pl[4][4];
        #pragma unroll
        for (int nf = 0; nf < 8; nf++) {
            const float e0 = __expf(sac[nf][0] - mn0);
            const float e1 = __expf(sac[nf][1] - mn0);
            const float e2 = __expf(sac[nf][2] - mn1);
            const float e3 = __expf(sac[nf][3] - mn1);
            s0 += e0 + e1; s1 += e2 + e3;
            uint32_t hi0, lo0, hi1, lo1;
            split_pack(e0, e1, hi0, lo0);
            split_pack(e2, e3, hi1, lo1);
            ph[nf >> 1][(nf & 1) * 2 + 0] = hi0;
            ph[nf >> 1][(nf & 1) * 2 + 1] = hi1;
            pl[nf >> 1][(nf & 1) * 2 + 0] = lo0;
            pl[nf >> 1][(nf & 1) * 2 + 1] = lo1;
        }
        s0 += __shfl_xor_sync(0xffffffffu, s0, 1);
        s0 += __shfl_xor_sync(0xffffffffu, s0, 2);
        s1 += __shfl_xor_sync(0xffffffffu, s1, 1);
        s1 += __shfl_xor_sync(0xffffffffu, s1, 2);
        l0 = l0 * c0 + s0; l1 = l1 * c1 + s1;
        m0 = mn0; m1 = mn1;
        #pragma unroll
        for (int nf = 0; nf < 8; nf++) {
            oac[nf][0] *= c0; oac[nf][1] *= c0;
            oac[nf][2] *= c1; oac[nf][3] *= c1;
        }

        // ---- O += P @ V : ph@vh + pl@vh + ph@vl (P from registers) ----
        #pragma unroll
        for (int ks = 0; ks < 4; ks++) {
            #pragma unroll
            for (int u = 0; u < 4; u++) {
                uint32_t vh[4], vl[4];
                ldm_x4_t(vh, vA[u] + ks * (16 * FL * 2));
                ldm_x4_t(vl, vA[u] + ks * (16 * FL * 2) + VLOFF);
                mma_bf16_16x8x16(oac[2*u],     ph[ks], vh);
                mma_bf16_16x8x16(oac[2*u],     pl[ks], vh);
                mma_bf16_16x8x16(oac[2*u],     ph[ks], vl);
                mma_bf16_16x8x16(oac[2*u + 1], ph[ks], vh + 2);
                mma_bf16_16x8x16(oac[2*u + 1], pl[ks], vh + 2);
                mma_bf16_16x8x16(oac[2*u + 1], ph[ks], vl + 2);
            }
        }
    }

    // epilogue: merged-head context [B,S,1024]
    const float il0 = 1.0f / l0, il1 = 1.0f / l1;
    const int row0 = qt*FQ + w*16 + g;
    float* ob = g_ctx + ((size_t)b*SEQ + row0) * D_MODEL + h*DEPTH;
    #pragma unroll
    for (int nf = 0; nf < 8; nf++) {
        const int c = nf*8 + 2*tg;
        float2 o0; o0.x = oac[nf][0] * il0; o0.y = oac[nf][1] * il0;
        float2 o1; o1.x = oac[nf][2] * il1; o1.y = oac[nf][3] * il1;
        *(float2*)(ob + c) = o0;
        *(float2*)(ob + (size_t)8 * D_MODEL + c) = o1;
    }
}

// ---------------------------------------------------------------------------
extern "C" void kernel_launch(void* const* d_in, const int* in_sizes, int n_in,
                              void* d_out, int out_size) {
    const float* query = (const float*)d_in[0];
    const float* key   = (const float*)d_in[1];
    const float* value = (const float*)d_in[2];
    const int*   mask  = (const int*)  d_in[3];
    const float* Wq = (const float*)d_in[4];
    const float* bq = (const float*)d_in[5];
    const float* Wk = (const float*)d_in[6];
    const float* bk = (const float*)d_in[7];
    const float* Wv = (const float*)d_in[8];
    const float* bv = (const float*)d_in[9];
    const float* Wo = (const float*)d_in[10];
    const float* bo = (const float*)d_in[11];
    float* out = (float*)d_out;

    cudaFuncSetAttribute(proj_qkv, cudaFuncAttributeMaxDynamicSharedMemorySize, PROJ_SMEM);
    cudaFuncSetAttribute(proj_o,   cudaFuncAttributeMaxDynamicSharedMemorySize, PROJ_SMEM);
    cudaFuncSetAttribute(flash_mma, cudaFuncAttributeMaxDynamicSharedMemorySize, FLASH_SMEM);

    const dim3 gq(D_MODEL / PBN, MTOT / PBM, 3);   // (8, 32, 3)
    proj_qkv<<<gq, 256, PROJ_SMEM>>>(query, key, value, Wq, bq, Wk, bk, Wv, bv);

    flash_mma<<<dim3(SEQ/FQ, NHEADS, BATCH), 256, FLASH_SMEM>>>(mask);

    proj_o<<<dim3(D_MODEL / PBN, MTOT / PBM), 256, PROJ_SMEM>>>(Wo, bo, out);
}

// round 13
// speedup vs baseline: 1.1549x; 1.1549x over previous
#include <cuda_runtime.h>
#include <cuda_bf16.h>
#include <cstdint>
#include <math.h>

#define D_MODEL 1024
#define NHEADS  16
#define DEPTH   64
#define BATCH   2
#define SEQ     2048
#define MTOT    (BATCH*SEQ)   // 4096

// ---------------- scratch (device globals; no allocations allowed) ----------
__device__ float g_q[BATCH*NHEADS*SEQ*DEPTH];   // 16 MB, [B,H,S,64]
__device__ float g_k[BATCH*NHEADS*SEQ*DEPTH];
__device__ float g_v[BATCH*NHEADS*SEQ*DEPTH];
__device__ float g_ctx[BATCH*SEQ*D_MODEL];      // 16 MB, [B,S,1024]

// ---------------- helpers ----------------------------------------------------
__device__ __forceinline__ uint32_t f2tf32(float x) {
    uint32_t r;
    asm("cvt.rna.tf32.f32 %0, %1;" : "=r"(r) : "f"(x));
    return r;
}
__device__ __forceinline__ void mma_tf32_16x8x8(float* d, const uint32_t* a,
                                                const uint32_t* b) {
    asm volatile(
        "mma.sync.aligned.m16n8k8.row.col.f32.tf32.tf32.f32 "
        "{%0,%1,%2,%3}, {%4,%5,%6,%7}, {%8,%9}, {%0,%1,%2,%3};"
        : "+f"(d[0]), "+f"(d[1]), "+f"(d[2]), "+f"(d[3])
        : "r"(a[0]), "r"(a[1]), "r"(a[2]), "r"(a[3]), "r"(b[0]), "r"(b[1]));
}
__device__ __forceinline__ void mma_bf16_16x8x16(float* d, const uint32_t* a,
                                                 const uint32_t* b) {
    asm volatile(
        "mma.sync.aligned.m16n8k16.row.col.f32.bf16.bf16.f32 "
        "{%0,%1,%2,%3}, {%4,%5,%6,%7}, {%8,%9}, {%0,%1,%2,%3};"
        : "+f"(d[0]), "+f"(d[1]), "+f"(d[2]), "+f"(d[3])
        : "r"(a[0]), "r"(a[1]), "r"(a[2]), "r"(a[3]), "r"(b[0]), "r"(b[1]));
}
__device__ __forceinline__ void ldm_x4(uint32_t* r, uint32_t saddr) {
    asm volatile("ldmatrix.sync.aligned.m8n8.x4.shared.b16 {%0,%1,%2,%3}, [%4];"
        : "=r"(r[0]), "=r"(r[1]), "=r"(r[2]), "=r"(r[3]) : "r"(saddr));
}
__device__ __forceinline__ void ldm_x4_t(uint32_t* r, uint32_t saddr) {
    asm volatile("ldmatrix.sync.aligned.m8n8.x4.trans.shared.b16 {%0,%1,%2,%3}, [%4];"
        : "=r"(r[0]), "=r"(r[1]), "=r"(r[2]), "=r"(r[3]) : "r"(saddr));
}
__device__ __forceinline__ uint32_t smem_u32(const void* p) {
    uint32_t a;
    asm("{ .reg .u64 t; cvta.to.shared.u64 t, %1; cvt.u32.u64 %0, t; }"
        : "=r"(a) : "l"(p));
    return a;
}
__device__ __forceinline__ uint32_t bf2pack(float a, float b) {
    uint32_t p;
    asm("cvt.rn.bf16x2.f32 %0, %1, %2;" : "=r"(p) : "f"(b), "f"(a));
    return p;
}
__device__ __forceinline__ void split_pack(float a, float b, uint32_t& hi, uint32_t& lo) {
    hi = bf2pack(a, b);
    const float fa = __uint_as_float(hi << 16);
    const float fb = __uint_as_float(hi & 0xffff0000u);
    lo = bf2pack(a - fa, b - fb);
}
#define CP_ASYNC16(sa, ga) \
    asm volatile("cp.async.ca.shared.global [%0], [%1], 16;" :: "r"(sa), "l"(ga))
#define CP_COMMIT() asm volatile("cp.async.commit_group;" ::: "memory")
#define CP_WAIT(n)  asm volatile("cp.async.wait_group %0;" :: "n"(n) : "memory")

// ============ tf32 tensor-core projection (cp.async pipelined, R10) =========
constexpr int PBM = 128, PBN = 128, PBK = 32, PLD = PBK + 4;   // PLD=36
constexpr int PROJ_STAGE = PBM * PLD;                           // floats
constexpr int PROJ_SMEM  = 4 * PROJ_STAGE * 4;                  // 73728 bytes

template<int SPLIT>
__device__ __forceinline__
void proj_body(float* smf, const float* __restrict__ A, const float* __restrict__ W,
               const float* __restrict__ bias, float* __restrict__ out) {
    const int tid  = threadIdx.x;
    const int wid  = tid >> 5;
    const int lane = tid & 31;
    const int g    = lane >> 2;
    const int tg   = lane & 3;
    const int wm   = wid >> 2;
    const int wn   = wid & 3;
    const int bm   = blockIdx.y * PBM;
    const int bn   = blockIdx.x * PBN;

    const int lrow8 = lane & 7;
    const int lhalf = (lane >> 3) & 1;
    const int lquad = lane >> 4;

    float* As0 = smf;
    float* Bs0 = smf + 2 * PROJ_STAGE;
    const uint32_t smb = smem_u32(smf);

    uint32_t aAddr[4], bAddr[2];
    #pragma unroll
    for (int mi = 0; mi < 4; mi++)
        aAddr[mi] = smb + ((wm*64 + mi*16 + lhalf*8 + lrow8) * PLD + lquad*4) * 4;
    #pragma unroll
    for (int u = 0; u < 2; u++)
        bAddr[u] = smb + (2*PROJ_STAGE + (wn*32 + (2*u + lquad)*8 + lrow8) * PLD + lhalf*4) * 4;

    float acc[4][4][4] = {};

    auto issue = [&](int s) {
        const int buf = s & 1;
        const int k0  = s * PBK;
        float* As = As0 + buf * PROJ_STAGE;
        float* Bs = Bs0 + buf * PROJ_STAGE;
        #pragma unroll
        for (int i = 0; i < 4; i++) {
            const int idx = tid + i * 256;
            const int r = idx >> 3;
            const int c = (idx & 7) * 4;
            CP_ASYNC16(smem_u32(&As[r * PLD + c]), A + (size_t)(bm + r) * D_MODEL + k0 + c);
            CP_ASYNC16(smem_u32(&Bs[r * PLD + c]), W + (size_t)(bn + r) * D_MODEL + k0 + c);
        }
        CP_COMMIT();
    };

    issue(0);
    for (int s = 0; s < D_MODEL / PBK; s++) {
        const uint32_t bufo = (uint32_t)(s & 1) * PROJ_STAGE * 4;
        if (s + 1 < D_MODEL / PBK) { issue(s + 1); CP_WAIT(1); }
        else                       { CP_WAIT(0); }
        __syncthreads();

        #pragma unroll
        for (int ks = 0; ks < PBK; ks += 8) {
            uint32_t araw[4][4], braw[2][4];
            #pragma unroll
            for (int mi = 0; mi < 4; mi++) ldm_x4(araw[mi], aAddr[mi] + bufo + ks*4);
            #pragma unroll
            for (int u = 0; u < 2; u++)    ldm_x4(braw[u],  bAddr[u]  + bufo + ks*4);

            uint32_t afr[4][4], bfr[4][2];
            #pragma unroll
            for (int mi = 0; mi < 4; mi++)
                #pragma unroll
                for (int e = 0; e < 4; e++)
                    afr[mi][e] = f2tf32(__uint_as_float(araw[mi][e]));
            #pragma unroll
            for (int u = 0; u < 2; u++) {
                bfr[2*u  ][0] = f2tf32(__uint_as_float(braw[u][0]));
                bfr[2*u  ][1] = f2tf32(__uint_as_float(braw[u][1]));
                bfr[2*u+1][0] = f2tf32(__uint_as_float(braw[u][2]));
                bfr[2*u+1][1] = f2tf32(__uint_as_float(braw[u][3]));
            }
            #pragma unroll
            for (int mi = 0; mi < 4; mi++)
                #pragma unroll
                for (int ni = 0; ni < 4; ni++)
                    mma_tf32_16x8x8(acc[mi][ni], afr[mi], bfr[ni]);
        }
        __syncthreads();
    }

    #pragma unroll
    for (int mi = 0; mi < 4; mi++) {
        #pragma unroll
        for (int ni = 0; ni < 4; ni++) {
            const int col = bn + wn * 32 + ni * 8 + tg * 2;
            const float2 bv = *(const float2*)(bias + col);
            #pragma unroll
            for (int half = 0; half < 2; half++) {
                const int m = bm + wm * 64 + mi * 16 + g + half * 8;
                float2 o;
                o.x = acc[mi][ni][half * 2 + 0] + bv.x;
                o.y = acc[mi][ni][half * 2 + 1] + bv.y;
                if (SPLIT) {
                    const int b = m >> 11, sq = m & 2047;
                    const int h = col >> 6, d = col & 63;
                    *(float2*)(out + (((size_t)(b * NHEADS + h) * SEQ) + sq) * DEPTH + d) = o;
                } else {
                    *(float2*)(out + (size_t)m * D_MODEL + col) = o;
                }
            }
        }
    }
}

__global__ __launch_bounds__(256)
void proj_qkv(const float* __restrict__ q, const float* __restrict__ k,
              const float* __restrict__ v,
              const float* __restrict__ Wq, const float* __restrict__ bq,
              const float* __restrict__ Wk, const float* __restrict__ bk,
              const float* __restrict__ Wv, const float* __restrict__ bv) {
    extern __shared__ float smf[];
    const float *A, *W, *bias;
    float* out;
    if (blockIdx.z == 0)      { A = q; W = Wq; bias = bq; out = g_q; }
    else if (blockIdx.z == 1) { A = k; W = Wk; bias = bk; out = g_k; }
    else                      { A = v; W = Wv; bias = bv; out = g_v; }
    proj_body<1>(smf, A, W, bias, out);
}

__global__ __launch_bounds__(256)
void proj_o(const float* __restrict__ W, const float* __restrict__ bias,
            float* __restrict__ out) {
    extern __shared__ float smf[];
    proj_body<0>(smf, g_ctx, W, bias, out);
}

// ================= flash attention v8: split-bf16, P in registers (R12) =====
constexpr int FQ  = 128;
constexpr int FK  = 64;
constexpr int FL  = 72;                       // row stride in bf16 units (144B)

constexpr int W_QH = 0;
constexpr int W_QL = W_QH + FQ * FL;          // 9216
constexpr int W_KH = W_QL + FQ * FL;          // 18432
constexpr int W_KL = W_KH + FK * FL;          // 23040
constexpr int W_VH = W_KL + FK * FL;          // 27648
constexpr int W_VL = W_VH + FK * FL;          // 32256
constexpr int SM_END = W_VL + FK * FL;        // 36864 bf16 units
constexpr int PEN_B  = SM_END * 2;
constexpr int FLASH_SMEM = PEN_B + FK * 4;    // 73984 bytes

constexpr uint32_t QLOFF = (W_QL - W_QH) * 2;
constexpr uint32_t KLOFF = (W_KL - W_KH) * 2;
constexpr uint32_t VLOFF = (W_VL - W_VH) * 2;

__global__ __launch_bounds__(256, 2)
void flash_mma(const int* __restrict__ mask) {
    extern __shared__ uint32_t sw[];
    uint16_t* sb = (uint16_t*)sw;
    float* pen = (float*)((char*)sw + PEN_B);

    const int qt = blockIdx.x, h = blockIdx.y, b = blockIdx.z;
    const int tid  = threadIdx.x;
    const int w    = tid >> 5;
    const int lane = tid & 31;
    const int tg   = lane & 3;
    const int g    = lane >> 2;

    const uint32_t swb = smem_u32(sw);
    const uint32_t arow = w*16 + (lane & 15);
    const uint32_t acol = (lane >> 4) * 8;
    const uint32_t qA = swb + (W_QH + arow * FL + acol) * 2;
    uint32_t kA[4];
    #pragma unroll
    for (int u = 0; u < 4; u++)
        kA[u] = swb + (W_KH + (u*16 + (lane >> 4) * 8 + (lane & 7)) * FL
                       + ((lane >> 3) & 1) * 8) * 2;
    uint32_t vA[4];
    #pragma unroll
    for (int u = 0; u < 4; u++)
        vA[u] = swb + (W_VH + (((lane >> 3) & 1) * 8 + (lane & 7)) * FL
                       + u*16 + (lane >> 4) * 8) * 2;

    const float* qbase = g_q + ((size_t)(b*NHEADS + h) * SEQ + qt*FQ) * DEPTH;
    const float* kbase = g_k + (size_t)(b*NHEADS + h) * SEQ * DEPTH;
    const float* vbase = g_v + (size_t)(b*NHEADS + h) * SEQ * DEPTH;

    // stage Q (scaled by 1/8), split bf16 hi/lo
    #pragma unroll
    for (int i = 0; i < 8; i++) {
        const int idx = tid + i * 256;
        const int r = idx >> 4, c4 = (idx & 15) << 2;
        float4 v = *(const float4*)(qbase + r * DEPTH + c4);
        v.x *= 0.125f; v.y *= 0.125f; v.z *= 0.125f; v.w *= 0.125f;
        uint2 hi, lo;
        split_pack(v.x, v.y, hi.x, lo.x);
        split_pack(v.z, v.w, hi.y, lo.y);
        *(uint2*)(sb + W_QH + r * FL + c4) = hi;
        *(uint2*)(sb + W_QL + r * FL + c4) = lo;
    }

    // prefetch K/V tile 0 + mask word
    float4 kreg[4], vreg[4];
    #pragma unroll
    for (int j = 0; j < 4; j++) {
        const int slot = tid + j * 256;
        const int r = slot >> 4, c4 = (slot & 15) << 2;
        kreg[j] = *(const float4*)(kbase + (size_t)r * DEPTH + c4);
        vreg[j] = *(const float4*)(vbase + (size_t)r * DEPTH + c4);
    }
    int pmask = (tid < FK) ? mask[b*SEQ + tid] : 0;

    float m0 = -1e30f, m1 = -1e30f, l0 = 0.f, l1 = 0.f;
    float oac[8][4] = {};

    for (int kt = 0; kt < SEQ / FK; kt++) {
        __syncthreads();
        #pragma unroll
        for (int j = 0; j < 4; j++) {
            const int slot = tid + j * 256;
            const int r = slot >> 4, c4 = (slot & 15) << 2;
            uint2 khi, klo, vhi, vlo;
            split_pack(kreg[j].x, kreg[j].y, khi.x, klo.x);
            split_pack(kreg[j].z, kreg[j].w, khi.y, klo.y);
            split_pack(vreg[j].x, vreg[j].y, vhi.x, vlo.x);
            split_pack(vreg[j].z, vreg[j].w, vhi.y, vlo.y);
            *(uint2*)(sb + W_KH + r * FL + c4) = khi;
            *(uint2*)(sb + W_KL + r * FL + c4) = klo;
            *(uint2*)(sb + W_VH + r * FL + c4) = vhi;
            *(uint2*)(sb + W_VL + r * FL + c4) = vlo;
        }
        if (tid < FK)
            pen[tid] = -1e9f * (float)pmask;
        __syncthreads();

        // prefetch next tile (overlaps with MMAs)
        if (kt + 1 < SEQ / FK) {
            const float* kb2 = kbase + (size_t)(kt + 1) * FK * DEPTH;
            const float* vb2 = vbase + (size_t)(kt + 1) * FK * DEPTH;
            #pragma unroll
            for (int j = 0; j < 4; j++) {
                const int slot = tid + j * 256;
                const int r = slot >> 4, c4 = (slot & 15) << 2;
                kreg[j] = *(const float4*)(kb2 + (size_t)r * DEPTH + c4);
                vreg[j] = *(const float4*)(vb2 + (size_t)r * DEPTH + c4);
            }
            if (tid < FK) pmask = mask[b*SEQ + (kt + 1)*FK + tid];
        }

        // ---- S = Q @ K^T : qh@kh + ql@kh + qh@kl ----
        float sac[8][4] = {};
        #pragma unroll
        for (int ks = 0; ks < 4; ks++) {
            uint32_t qh[4], ql[4];
            ldm_x4(qh, qA + ks * 32);
            ldm_x4(ql, qA + ks * 32 + QLOFF);
            #pragma unroll
            for (int u = 0; u < 4; u++) {
                uint32_t kh[4], kl[4];
                ldm_x4(kh, kA[u] + ks * 32);
                ldm_x4(kl, kA[u] + ks * 32 + KLOFF);
                mma_bf16_16x8x16(sac[2*u],     qh, kh);
                mma_bf16_16x8x16(sac[2*u],     ql, kh);
                mma_bf16_16x8x16(sac[2*u],     qh, kl);
                mma_bf16_16x8x16(sac[2*u + 1], qh, kh + 2);
                mma_bf16_16x8x16(sac[2*u + 1], ql, kh + 2);
                mma_bf16_16x8x16(sac[2*u + 1], qh, kl + 2);
            }
        }

        // ---- mask + online softmax; pack P hi/lo directly into A-fragments --
        #pragma unroll
        for (int nf = 0; nf < 8; nf++) {
            const float2 pe = *(const float2*)&pen[nf*8 + 2*tg];
            sac[nf][0] += pe.x; sac[nf][1] += pe.y;
            sac[nf][2] += pe.x; sac[nf][3] += pe.y;
        }
        float mx0 = -1e30f, mx1 = -1e30f;
        #pragma unroll
        for (int nf = 0; nf < 8; nf++) {
            mx0 = fmaxf(mx0, fmaxf(sac[nf][0], sac[nf][1]));
            mx1 = fmaxf(mx1, fmaxf(sac[nf][2], sac[nf][3]));
        }
        mx0 = fmaxf(mx0, __shfl_xor_sync(0xffffffffu, mx0, 1));
        mx0 = fmaxf(mx0, __shfl_xor_sync(0xffffffffu, mx0, 2));
        mx1 = fmaxf(mx1, __shfl_xor_sync(0xffffffffu, mx1, 1));
        mx1 = fmaxf(mx1, __shfl_xor_sync(0xffffffffu, mx1, 2));
        const float mn0 = fmaxf(m0, mx0), mn1 = fmaxf(m1, mx1);
        const float c0 = __expf(m0 - mn0), c1 = __expf(m1 - mn1);
        float s0 = 0.f, s1 = 0.f;
        uint32_t ph[4][4], pl[4][4];
        #pragma unroll
        for (int nf = 0; nf < 8; nf++) {
            const float e0 = __expf(sac[nf][0] - mn0);
            const float e1 = __expf(sac[nf][1] - mn0);
            const float e2 = __expf(sac[nf][2] - mn1);
            const float e3 = __expf(sac[nf][3] - mn1);
            s0 += e0 + e1; s1 += e2 + e3;
            uint32_t hi0, lo0, hi1, lo1;
            split_pack(e0, e1, hi0, lo0);
            split_pack(e2, e3, hi1, lo1);
            ph[nf >> 1][(nf & 1) * 2 + 0] = hi0;
            ph[nf >> 1][(nf & 1) * 2 + 1] = hi1;
            pl[nf >> 1][(nf & 1) * 2 + 0] = lo0;
            pl[nf >> 1][(nf & 1) * 2 + 1] = lo1;
        }
        s0 += __shfl_xor_sync(0xffffffffu, s0, 1);
        s0 += __shfl_xor_sync(0xffffffffu, s0, 2);
        s1 += __shfl_xor_sync(0xffffffffu, s1, 1);
        s1 += __shfl_xor_sync(0xffffffffu, s1, 2);
        l0 = l0 * c0 + s0; l1 = l1 * c1 + s1;
        m0 = mn0; m1 = mn1;
        #pragma unroll
        for (int nf = 0; nf < 8; nf++) {
            oac[nf][0] *= c0; oac[nf][1] *= c0;
            oac[nf][2] *= c1; oac[nf][3] *= c1;
        }

        // ---- O += P @ V : ph@vh + pl@vh + ph@vl (P from registers) ----
        #pragma unroll
        for (int ks = 0; ks < 4; ks++) {
            #pragma unroll
            for (int u = 0; u < 4; u++) {
                uint32_t vh[4], vl[4];
                ldm_x4_t(vh, vA[u] + ks * (16 * FL * 2));
                ldm_x4_t(vl, vA[u] + ks * (16 * FL * 2) + VLOFF);
                mma_bf16_16x8x16(oac[2*u],     ph[ks], vh);
                mma_bf16_16x8x16(oac[2*u],     pl[ks], vh);
                mma_bf16_16x8x16(oac[2*u],     ph[ks], vl);
                mma_bf16_16x8x16(oac[2*u + 1], ph[ks], vh + 2);
                mma_bf16_16x8x16(oac[2*u + 1], pl[ks], vh + 2);
                mma_bf16_16x8x16(oac[2*u + 1], ph[ks], vl + 2);
            }
        }
    }

    // epilogue: merged-head context [B,S,1024]
    const float il0 = 1.0f / l0, il1 = 1.0f / l1;
    const int row0 = qt*FQ + w*16 + g;
    float* ob = g_ctx + ((size_t)b*SEQ + row0) * D_MODEL + h*DEPTH;
    #pragma unroll
    for (int nf = 0; nf < 8; nf++) {
        const int c = nf*8 + 2*tg;
        float2 o0; o0.x = oac[nf][0] * il0; o0.y = oac[nf][1] * il0;
        float2 o1; o1.x = oac[nf][2] * il1; o1.y = oac[nf][3] * il1;
        *(float2*)(ob + c) = o0;
        *(float2*)(ob + (size_t)8 * D_MODEL + c) = o1;
    }
}

// ---------------------------------------------------------------------------
extern "C" void kernel_launch(void* const* d_in, const int* in_sizes, int n_in,
                              void* d_out, int out_size) {
    const float* query = (const float*)d_in[0];
    const float* key   = (const float*)d_in[1];
    const float* value = (const float*)d_in[2];
    const int*   mask  = (const int*)  d_in[3];
    const float* Wq = (const float*)d_in[4];
    const float* bq = (const float*)d_in[5];
    const float* Wk = (const float*)d_in[6];
    const float* bk = (const float*)d_in[7];
    const float* Wv = (const float*)d_in[8];
    const float* bv = (const float*)d_in[9];
    const float* Wo = (const float*)d_in[10];
    const float* bo = (const float*)d_in[11];
    float* out = (float*)d_out;

    cudaFuncSetAttribute(proj_qkv, cudaFuncAttributeMaxDynamicSharedMemorySize, PROJ_SMEM);
    cudaFuncSetAttribute(proj_o,   cudaFuncAttributeMaxDynamicSharedMemorySize, PROJ_SMEM);
    cudaFuncSetAttribute(flash_mma, cudaFuncAttributeMaxDynamicSharedMemorySize, FLASH_SMEM);

    const dim3 gq(D_MODEL / PBN, MTOT / PBM, 3);   // (8, 32, 3)
    proj_qkv<<<gq, 256, PROJ_SMEM>>>(query, key, value, Wq, bq, Wk, bk, Wv, bv);

    flash_mma<<<dim3(SEQ/FQ, NHEADS, BATCH), 256, FLASH_SMEM>>>(mask);

    proj_o<<<dim3(D_MODEL / PBN, MTOT / PBM), 256, PROJ_SMEM>>>(Wo, bo, out);
}

// round 14
// speedup vs baseline: 1.1580x; 1.0027x over previous
#include <cuda_runtime.h>
#include <cuda_bf16.h>
#include <cstdint>
#include <math.h>

#define D_MODEL 1024
#define NHEADS  16
#define DEPTH   64
#define BATCH   2
#define SEQ     2048
#define MTOT    (BATCH*SEQ)   // 4096

// ---------------- scratch (device globals; no allocations allowed) ----------
__device__ float g_q[BATCH*NHEADS*SEQ*DEPTH];   // 16 MB, [B,H,S,64]
__device__ float g_k[BATCH*NHEADS*SEQ*DEPTH];
__device__ float g_v[BATCH*NHEADS*SEQ*DEPTH];
__device__ float g_ctx[BATCH*SEQ*D_MODEL];      // 16 MB, [B,S,1024]

// ---------------- helpers ----------------------------------------------------
__device__ __forceinline__ uint32_t f2tf32(float x) {
    uint32_t r;
    asm("cvt.rna.tf32.f32 %0, %1;" : "=r"(r) : "f"(x));
    return r;
}
__device__ __forceinline__ void mma_tf32_16x8x8(float* d, const uint32_t* a,
                                                const uint32_t* b) {
    asm volatile(
        "mma.sync.aligned.m16n8k8.row.col.f32.tf32.tf32.f32 "
        "{%0,%1,%2,%3}, {%4,%5,%6,%7}, {%8,%9}, {%0,%1,%2,%3};"
        : "+f"(d[0]), "+f"(d[1]), "+f"(d[2]), "+f"(d[3])
        : "r"(a[0]), "r"(a[1]), "r"(a[2]), "r"(a[3]), "r"(b[0]), "r"(b[1]));
}
__device__ __forceinline__ void mma_bf16_16x8x16(float* d, const uint32_t* a,
                                                 const uint32_t* b) {
    asm volatile(
        "mma.sync.aligned.m16n8k16.row.col.f32.bf16.bf16.f32 "
        "{%0,%1,%2,%3}, {%4,%5,%6,%7}, {%8,%9}, {%0,%1,%2,%3};"
        : "+f"(d[0]), "+f"(d[1]), "+f"(d[2]), "+f"(d[3])
        : "r"(a[0]), "r"(a[1]), "r"(a[2]), "r"(a[3]), "r"(b[0]), "r"(b[1]));
}
__device__ __forceinline__ void ldm_x4(uint32_t* r, uint32_t saddr) {
    asm volatile("ldmatrix.sync.aligned.m8n8.x4.shared.b16 {%0,%1,%2,%3}, [%4];"
        : "=r"(r[0]), "=r"(r[1]), "=r"(r[2]), "=r"(r[3]) : "r"(saddr));
}
__device__ __forceinline__ void ldm_x4_t(uint32_t* r, uint32_t saddr) {
    asm volatile("ldmatrix.sync.aligned.m8n8.x4.trans.shared.b16 {%0,%1,%2,%3}, [%4];"
        : "=r"(r[0]), "=r"(r[1]), "=r"(r[2]), "=r"(r[3]) : "r"(saddr));
}
__device__ __forceinline__ uint32_t smem_u32(const void* p) {
    uint32_t a;
    asm("{ .reg .u64 t; cvta.to.shared.u64 t, %1; cvt.u32.u64 %0, t; }"
        : "=r"(a) : "l"(p));
    return a;
}
__device__ __forceinline__ uint32_t bf2pack(float a, float b) {
    uint32_t p;
    asm("cvt.rn.bf16x2.f32 %0, %1, %2;" : "=r"(p) : "f"(b), "f"(a));
    return p;
}
__device__ __forceinline__ void split_pack(float a, float b, uint32_t& hi, uint32_t& lo) {
    hi = bf2pack(a, b);
    const float fa = __uint_as_float(hi << 16);
    const float fb = __uint_as_float(hi & 0xffff0000u);
    lo = bf2pack(a - fa, b - fb);
}
#define CP_ASYNC16(sa, ga) \
    asm volatile("cp.async.ca.shared.global [%0], [%1], 16;" :: "r"(sa), "l"(ga))
#define CP_COMMIT() asm volatile("cp.async.commit_group;" ::: "memory")
#define CP_WAIT(n)  asm volatile("cp.async.wait_group %0;" :: "n"(n) : "memory")

// ============ tf32 tensor-core projection (cp.async pipelined, R10) =========
constexpr int PBM = 128, PBN = 128, PBK = 32, PLD = PBK + 4;   // PLD=36
constexpr int PROJ_STAGE = PBM * PLD;                           // floats
constexpr int PROJ_SMEM  = 4 * PROJ_STAGE * 4;                  // 73728 bytes

template<int SPLIT>
__device__ __forceinline__
void proj_body(float* smf, const float* __restrict__ A, const float* __restrict__ W,
               const float* __restrict__ bias, float* __restrict__ out) {
    const int tid  = threadIdx.x;
    const int wid  = tid >> 5;
    const int lane = tid & 31;
    const int g    = lane >> 2;
    const int tg   = lane & 3;
    const int wm   = wid >> 2;
    const int wn   = wid & 3;
    const int bm   = blockIdx.y * PBM;
    const int bn   = blockIdx.x * PBN;

    const int lrow8 = lane & 7;
    const int lhalf = (lane >> 3) & 1;
    const int lquad = lane >> 4;

    float* As0 = smf;
    float* Bs0 = smf + 2 * PROJ_STAGE;
    const uint32_t smb = smem_u32(smf);

    uint32_t aAddr[4], bAddr[2];
    #pragma unroll
    for (int mi = 0; mi < 4; mi++)
        aAddr[mi] = smb + ((wm*64 + mi*16 + lhalf*8 + lrow8) * PLD + lquad*4) * 4;
    #pragma unroll
    for (int u = 0; u < 2; u++)
        bAddr[u] = smb + (2*PROJ_STAGE + (wn*32 + (2*u + lquad)*8 + lrow8) * PLD + lhalf*4) * 4;

    float acc[4][4][4] = {};

    auto issue = [&](int s) {
        const int buf = s & 1;
        const int k0  = s * PBK;
        float* As = As0 + buf * PROJ_STAGE;
        float* Bs = Bs0 + buf * PROJ_STAGE;
        #pragma unroll
        for (int i = 0; i < 4; i++) {
            const int idx = tid + i * 256;
            const int r = idx >> 3;
            const int c = (idx & 7) * 4;
            CP_ASYNC16(smem_u32(&As[r * PLD + c]), A + (size_t)(bm + r) * D_MODEL + k0 + c);
            CP_ASYNC16(smem_u32(&Bs[r * PLD + c]), W + (size_t)(bn + r) * D_MODEL + k0 + c);
        }
        CP_COMMIT();
    };

    issue(0);
    for (int s = 0; s < D_MODEL / PBK; s++) {
        const uint32_t bufo = (uint32_t)(s & 1) * PROJ_STAGE * 4;
        if (s + 1 < D_MODEL / PBK) { issue(s + 1); CP_WAIT(1); }
        else                       { CP_WAIT(0); }
        __syncthreads();

        #pragma unroll
        for (int ks = 0; ks < PBK; ks += 8) {
            uint32_t araw[4][4], braw[2][4];
            #pragma unroll
            for (int mi = 0; mi < 4; mi++) ldm_x4(araw[mi], aAddr[mi] + bufo + ks*4);
            #pragma unroll
            for (int u = 0; u < 2; u++)    ldm_x4(braw[u],  bAddr[u]  + bufo + ks*4);

            uint32_t afr[4][4], bfr[4][2];
            #pragma unroll
            for (int mi = 0; mi < 4; mi++)
                #pragma unroll
                for (int e = 0; e < 4; e++)
                    afr[mi][e] = f2tf32(__uint_as_float(araw[mi][e]));
            #pragma unroll
            for (int u = 0; u < 2; u++) {
                bfr[2*u  ][0] = f2tf32(__uint_as_float(braw[u][0]));
                bfr[2*u  ][1] = f2tf32(__uint_as_float(braw[u][1]));
                bfr[2*u+1][0] = f2tf32(__uint_as_float(braw[u][2]));
                bfr[2*u+1][1] = f2tf32(__uint_as_float(braw[u][3]));
            }
            #pragma unroll
            for (int mi = 0; mi < 4; mi++)
                #pragma unroll
                for (int ni = 0; ni < 4; ni++)
                    mma_tf32_16x8x8(acc[mi][ni], afr[mi], bfr[ni]);
        }
        __syncthreads();
    }

    #pragma unroll
    for (int mi = 0; mi < 4; mi++) {
        #pragma unroll
        for (int ni = 0; ni < 4; ni++) {
            const int col = bn + wn * 32 + ni * 8 + tg * 2;
            const float2 bv = *(const float2*)(bias + col);
            #pragma unroll
            for (int half = 0; half < 2; half++) {
                const int m = bm + wm * 64 + mi * 16 + g + half * 8;
                float2 o;
                o.x = acc[mi][ni][half * 2 + 0] + bv.x;
                o.y = acc[mi][ni][half * 2 + 1] + bv.y;
                if (SPLIT) {
                    const int b = m >> 11, sq = m & 2047;
                    const int h = col >> 6, d = col & 63;
                    *(float2*)(out + (((size_t)(b * NHEADS + h) * SEQ) + sq) * DEPTH + d) = o;
                } else {
                    *(float2*)(out + (size_t)m * D_MODEL + col) = o;
                }
            }
        }
    }
}

__global__ __launch_bounds__(256)
void proj_qkv(const float* __restrict__ q, const float* __restrict__ k,
              const float* __restrict__ v,
              const float* __restrict__ Wq, const float* __restrict__ bq,
              const float* __restrict__ Wk, const float* __restrict__ bk,
              const float* __restrict__ Wv, const float* __restrict__ bv) {
    extern __shared__ float smf[];
    const float *A, *W, *bias;
    float* out;
    if (blockIdx.z == 0)      { A = q; W = Wq; bias = bq; out = g_q; }
    else if (blockIdx.z == 1) { A = k; W = Wk; bias = bk; out = g_k; }
    else                      { A = v; W = Wv; bias = bv; out = g_v; }
    proj_body<1>(smf, A, W, bias, out);
}

__global__ __launch_bounds__(256)
void proj_o(const float* __restrict__ W, const float* __restrict__ bias,
            float* __restrict__ out) {
    extern __shared__ float smf[];
    proj_body<0>(smf, g_ctx, W, bias, out);
}

// ================= flash attention v8: split-bf16, P in registers (R12) =====
constexpr int FQ  = 128;
constexpr int FK  = 64;
constexpr int FL  = 72;                       // row stride in bf16 units (144B)

constexpr int W_QH = 0;
constexpr int W_QL = W_QH + FQ * FL;          // 9216
constexpr int W_KH = W_QL + FQ * FL;          // 18432
constexpr int W_KL = W_KH + FK * FL;          // 23040
constexpr int W_VH = W_KL + FK * FL;          // 27648
constexpr int W_VL = W_VH + FK * FL;          // 32256
constexpr int SM_END = W_VL + FK * FL;        // 36864 bf16 units
constexpr int PEN_B  = SM_END * 2;
constexpr int FLASH_SMEM = PEN_B + FK * 4;    // 73984 bytes

constexpr uint32_t QLOFF = (W_QL - W_QH) * 2;
constexpr uint32_t KLOFF = (W_KL - W_KH) * 2;
constexpr uint32_t VLOFF = (W_VL - W_VH) * 2;

__global__ __launch_bounds__(256, 2)
void flash_mma(const int* __restrict__ mask) {
    extern __shared__ uint32_t sw[];
    uint16_t* sb = (uint16_t*)sw;
    float* pen = (float*)((char*)sw + PEN_B);

    const int qt = blockIdx.x, h = blockIdx.y, b = blockIdx.z;
    const int tid  = threadIdx.x;
    const int w    = tid >> 5;
    const int lane = tid & 31;
    const int tg   = lane & 3;
    const int g    = lane >> 2;

    const uint32_t swb = smem_u32(sw);
    const uint32_t arow = w*16 + (lane & 15);
    const uint32_t acol = (lane >> 4) * 8;
    const uint32_t qA = swb + (W_QH + arow * FL + acol) * 2;
    uint32_t kA[4];
    #pragma unroll
    for (int u = 0; u < 4; u++)
        kA[u] = swb + (W_KH + (u*16 + (lane >> 4) * 8 + (lane & 7)) * FL
                       + ((lane >> 3) & 1) * 8) * 2;
    uint32_t vA[4];
    #pragma unroll
    for (int u = 0; u < 4; u++)
        vA[u] = swb + (W_VH + (((lane >> 3) & 1) * 8 + (lane & 7)) * FL
                       + u*16 + (lane >> 4) * 8) * 2;

    const float* qbase = g_q + ((size_t)(b*NHEADS + h) * SEQ + qt*FQ) * DEPTH;
    const float* kbase = g_k + (size_t)(b*NHEADS + h) * SEQ * DEPTH;
    const float* vbase = g_v + (size_t)(b*NHEADS + h) * SEQ * DEPTH;

    // stage Q (scaled by 1/8), split bf16 hi/lo
    #pragma unroll
    for (int i = 0; i < 8; i++) {
        const int idx = tid + i * 256;
        const int r = idx >> 4, c4 = (idx & 15) << 2;
        float4 v = *(const float4*)(qbase + r * DEPTH + c4);
        v.x *= 0.125f; v.y *= 0.125f; v.z *= 0.125f; v.w *= 0.125f;
        uint2 hi, lo;
        split_pack(v.x, v.y, hi.x, lo.x);
        split_pack(v.z, v.w, hi.y, lo.y);
        *(uint2*)(sb + W_QH + r * FL + c4) = hi;
        *(uint2*)(sb + W_QL + r * FL + c4) = lo;
    }

    // prefetch K/V tile 0 + mask word
    float4 kreg[4], vreg[4];
    #pragma unroll
    for (int j = 0; j < 4; j++) {
        const int slot = tid + j * 256;
        const int r = slot >> 4, c4 = (slot & 15) << 2;
        kreg[j] = *(const float4*)(kbase + (size_t)r * DEPTH + c4);
        vreg[j] = *(const float4*)(vbase + (size_t)r * DEPTH + c4);
    }
    int pmask = (tid < FK) ? mask[b*SEQ + tid] : 0;

    float m0 = -1e30f, m1 = -1e30f, l0 = 0.f, l1 = 0.f;
    float oac[8][4] = {};

    for (int kt = 0; kt < SEQ / FK; kt++) {
        __syncthreads();
        #pragma unroll
        for (int j = 0; j < 4; j++) {
            const int slot = tid + j * 256;
            const int r = slot >> 4, c4 = (slot & 15) << 2;
            uint2 khi, klo, vhi, vlo;
            split_pack(kreg[j].x, kreg[j].y, khi.x, klo.x);
            split_pack(kreg[j].z, kreg[j].w, khi.y, klo.y);
            split_pack(vreg[j].x, vreg[j].y, vhi.x, vlo.x);
            split_pack(vreg[j].z, vreg[j].w, vhi.y, vlo.y);
            *(uint2*)(sb + W_KH + r * FL + c4) = khi;
            *(uint2*)(sb + W_KL + r * FL + c4) = klo;
            *(uint2*)(sb + W_VH + r * FL + c4) = vhi;
            *(uint2*)(sb + W_VL + r * FL + c4) = vlo;
        }
        if (tid < FK)
            pen[tid] = -1e9f * (float)pmask;
        __syncthreads();

        // prefetch next tile (overlaps with MMAs)
        if (kt + 1 < SEQ / FK) {
            const float* kb2 = kbase + (size_t)(kt + 1) * FK * DEPTH;
            const float* vb2 = vbase + (size_t)(kt + 1) * FK * DEPTH;
            #pragma unroll
            for (int j = 0; j < 4; j++) {
                const int slot = tid + j * 256;
                const int r = slot >> 4, c4 = (slot & 15) << 2;
                kreg[j] = *(const float4*)(kb2 + (size_t)r * DEPTH + c4);
                vreg[j] = *(const float4*)(vb2 + (size_t)r * DEPTH + c4);
            }
            if (tid < FK) pmask = mask[b*SEQ + (kt + 1)*FK + tid];
        }

        // ---- S = Q @ K^T : qh@kh + ql@kh + qh@kl ----
        float sac[8][4] = {};
        #pragma unroll
        for (int ks = 0; ks < 4; ks++) {
            uint32_t qh[4], ql[4];
            ldm_x4(qh, qA + ks * 32);
            ldm_x4(ql, qA + ks * 32 + QLOFF);
            #pragma unroll
            for (int u = 0; u < 4; u++) {
                uint32_t kh[4], kl[4];
                ldm_x4(kh, kA[u] + ks * 32);
                ldm_x4(kl, kA[u] + ks * 32 + KLOFF);
                mma_bf16_16x8x16(sac[2*u],     qh, kh);
                mma_bf16_16x8x16(sac[2*u],     ql, kh);
                mma_bf16_16x8x16(sac[2*u],     qh, kl);
                mma_bf16_16x8x16(sac[2*u + 1], qh, kh + 2);
                mma_bf16_16x8x16(sac[2*u + 1], ql, kh + 2);
                mma_bf16_16x8x16(sac[2*u + 1], qh, kl + 2);
            }
        }

        // ---- mask + online softmax; pack P hi/lo directly into A-fragments --
        #pragma unroll
        for (int nf = 0; nf < 8; nf++) {
            const float2 pe = *(const float2*)&pen[nf*8 + 2*tg];
            sac[nf][0] += pe.x; sac[nf][1] += pe.y;
            sac[nf][2] += pe.x; sac[nf][3] += pe.y;
        }
        float mx0 = -1e30f, mx1 = -1e30f;
        #pragma unroll
        for (int nf = 0; nf < 8; nf++) {
            mx0 = fmaxf(mx0, fmaxf(sac[nf][0], sac[nf][1]));
            mx1 = fmaxf(mx1, fmaxf(sac[nf][2], sac[nf][3]));
        }
        mx0 = fmaxf(mx0, __shfl_xor_sync(0xffffffffu, mx0, 1));
        mx0 = fmaxf(mx0, __shfl_xor_sync(0xffffffffu, mx0, 2));
        mx1 = fmaxf(mx1, __shfl_xor_sync(0xffffffffu, mx1, 1));
        mx1 = fmaxf(mx1, __shfl_xor_sync(0xffffffffu, mx1, 2));
        const float mn0 = fmaxf(m0, mx0), mn1 = fmaxf(m1, mx1);
        const float c0 = __expf(m0 - mn0), c1 = __expf(m1 - mn1);
        float s0 = 0.f, s1 = 0.f;
        uint32_t ph[4][4], pl[4][4];
        #pragma unroll
        for (int nf = 0; nf < 8; nf++) {
            const float e0 = __expf(sac[nf][0] - mn0);
            const float e1 = __expf(sac[nf][1] - mn0);
            const float e2 = __expf(sac[nf][2] - mn1);
            const float e3 = __expf(sac[nf][3] - mn1);
            s0 += e0 + e1; s1 += e2 + e3;
            uint32_t hi0, lo0, hi1, lo1;
            split_pack(e0, e1, hi0, lo0);
            split_pack(e2, e3, hi1, lo1);
            ph[nf >> 1][(nf & 1) * 2 + 0] = hi0;
            ph[nf >> 1][(nf & 1) * 2 + 1] = hi1;
            pl[nf >> 1][(nf & 1) * 2 + 0] = lo0;
            pl[nf >> 1][(nf & 1) * 2 + 1] = lo1;
        }
        s0 += __shfl_xor_sync(0xffffffffu, s0, 1);
        s0 += __shfl_xor_sync(0xffffffffu, s0, 2);
        s1 += __shfl_xor_sync(0xffffffffu, s1, 1);
        s1 += __shfl_xor_sync(0xffffffffu, s1, 2);
        l0 = l0 * c0 + s0; l1 = l1 * c1 + s1;
        m0 = mn0; m1 = mn1;
        #pragma unroll
        for (int nf = 0; nf < 8; nf++) {
            oac[nf][0] *= c0; oac[nf][1] *= c0;
            oac[nf][2] *= c1; oac[nf][3] *= c1;
        }

        // ---- O += P @ V : ph@vh + pl@vh + ph@vl (P from registers) ----
        #pragma unroll
        for (int ks = 0; ks < 4; ks++) {
            #pragma unroll
            for (int u = 0; u < 4; u++) {
                uint32_t vh[4], vl[4];
                ldm_x4_t(vh, vA[u] + ks * (16 * FL * 2));
                ldm_x4_t(vl, vA[u] + ks * (16 * FL * 2) + VLOFF);
                mma_bf16_16x8x16(oac[2*u],     ph[ks], vh);
                mma_bf16_16x8x16(oac[2*u],     pl[ks], vh);
                mma_bf16_16x8x16(oac[2*u],     ph[ks], vl);
                mma_bf16_16x8x16(oac[2*u + 1], ph[ks], vh + 2);
                mma_bf16_16x8x16(oac[2*u + 1], pl[ks], vh + 2);
                mma_bf16_16x8x16(oac[2*u + 1], ph[ks], vl + 2);
            }
        }
    }

    // epilogue: merged-head context [B,S,1024]
    const float il0 = 1.0f / l0, il1 = 1.0f / l1;
    const int row0 = qt*FQ + w*16 + g;
    float* ob = g_ctx + ((size_t)b*SEQ + row0) * D_MODEL + h*DEPTH;
    #pragma unroll
    for (int nf = 0; nf < 8; nf++) {
        const int c = nf*8 + 2*tg;
        float2 o0; o0.x = oac[nf][0] * il0; o0.y = oac[nf][1] * il0;
        float2 o1; o1.x = oac[nf][2] * il1; o1.y = oac[nf][3] * il1;
        *(float2*)(ob + c) = o0;
        *(float2*)(ob + (size_t)8 * D_MODEL + c) = o1;
    }
}

// ---------------------------------------------------------------------------
extern "C" void kernel_launch(void* const* d_in, const int* in_sizes, int n_in,
                              void* d_out, int out_size) {
    const float* query = (const float*)d_in[0];
    const float* key   = (const float*)d_in[1];
    const float* value = (const float*)d_in[2];
    const int*   mask  = (const int*)  d_in[3];
    const float* Wq = (const float*)d_in[4];
    const float* bq = (const float*)d_in[5];
    const float* Wk = (const float*)d_in[6];
    const float* bk = (const float*)d_in[7];
    const float* Wv = (const float*)d_in[8];
    const float* bv = (const float*)d_in[9];
    const float* Wo = (const float*)d_in[10];
    const float* bo = (const float*)d_in[11];
    float* out = (float*)d_out;

    cudaFuncSetAttribute(proj_qkv, cudaFuncAttributeMaxDynamicSharedMemorySize, PROJ_SMEM);
    cudaFuncSetAttribute(proj_o,   cudaFuncAttributeMaxDynamicSharedMemorySize, PROJ_SMEM);
    cudaFuncSetAttribute(flash_mma, cudaFuncAttributeMaxDynamicSharedMemorySize, FLASH_SMEM);

    const dim3 gq(D_MODEL / PBN, MTOT / PBM, 3);   // (8, 32, 3)
    proj_qkv<<<gq, 256, PROJ_SMEM>>>(query, key, value, Wq, bq, Wk, bk, Wv, bv);

    flash_mma<<<dim3(SEQ/FQ, NHEADS, BATCH), 256, FLASH_SMEM>>>(mask);

    proj_o<<<dim3(D_MODEL / PBN, MTOT / PBM), 256, PROJ_SMEM>>>(Wo, bo, out);
}